// round 1
// baseline (speedup 1.0000x reference)
#include <cuda_runtime.h>

#define CDIM   128      // channels
#define NEXP   8        // experts
#define SPATIAL 32768   // T*H*W = 8*64*64
#define TILE_V 64       // voxels per block
#define PITCH  132      // smem row pitch (floats); %4==0 for float4, mod-32=4 limits conflicts
#define NT     256

__device__ __forceinline__ float dot4(float4 a, float4 b, float acc) {
    acc = fmaf(a.x, b.x, acc);
    acc = fmaf(a.y, b.y, acc);
    acc = fmaf(a.z, b.z, acc);
    acc = fmaf(a.w, b.w, acc);
    return acc;
}

__global__ __launch_bounds__(NT)
void moe_sparse_kernel(const float* __restrict__ x,
                       const float* __restrict__ gate_w,
                       const float* __restrict__ gate_b,
                       const float* __restrict__ w1,
                       const float* __restrict__ b1,
                       const float* __restrict__ w2,
                       const float* __restrict__ b2,
                       float* __restrict__ out)
{
    __shared__ float xs[TILE_V * PITCH];   // x tile, later reused as out tile
    __shared__ float gw[NEXP * CDIM];
    __shared__ float lgs[TILE_V * NEXP];
    __shared__ float hs[NT / 32][CDIM];    // per-warp h buffer
    __shared__ int   re[TILE_V][2];
    __shared__ float rp[TILE_V][2];

    const int tid = threadIdx.x;
    const int vg0 = blockIdx.x * TILE_V;
    const int b   = vg0 >> 15;             // vg0 / SPATIAL
    const int s0  = vg0 & (SPATIAL - 1);
    const float* xb = x + ((size_t)b * CDIM) * SPATIAL + s0;

    // --- stage gate weights ---
    for (int i = tid; i < NEXP * CDIM; i += NT) gw[i] = gate_w[i];

    // --- load x tile, transposed into xs[v][c] (coalesced gmem reads) ---
    const int c_sub = tid >> 6;            // 0..3
    const int iv    = tid & 63;            // voxel within tile
    #pragma unroll
    for (int cc = 0; cc < CDIM; cc += 4) {
        int c = cc + c_sub;
        xs[iv * PITCH + c] = xb[(size_t)c * SPATIAL + iv];
    }
    __syncthreads();

    // --- gate logits (fp32, 512 (v,e) pairs) ---
    for (int p = tid; p < TILE_V * NEXP; p += NT) {
        int v = p & (TILE_V - 1);
        int e = p >> 6;
        const float4* xv4 = (const float4*)(xs + v * PITCH);
        const float4* gw4 = (const float4*)(gw + e * CDIM);
        float acc = 0.f;
        #pragma unroll
        for (int j = 0; j < CDIM / 4; j++) acc = dot4(xv4[j], gw4[j], acc);
        lgs[v * NEXP + e] = acc + __ldg(gate_b + e);
    }
    __syncthreads();

    // --- top-2 + softmax (matches jax.lax.top_k tie-breaking: strict >, low idx wins) ---
    if (tid < TILE_V) {
        const float* l = lgs + tid * NEXP;
        int i0 = 0; float v0 = l[0];
        #pragma unroll
        for (int e = 1; e < NEXP; e++) { float t = l[e]; if (t > v0) { v0 = t; i0 = e; } }
        int i1 = -1; float v1 = -3.4e38f;
        #pragma unroll
        for (int e = 0; e < NEXP; e++) {
            if (e == i0) continue;
            float t = l[e]; if (t > v1) { v1 = t; i1 = e; }
        }
        float e1v = __expf(v1 - v0);
        float inv = 1.f / (1.f + e1v);
        re[tid][0] = i0;  re[tid][1] = i1;
        rp[tid][0] = inv; rp[tid][1] = e1v * inv;
    }
    __syncthreads();

    // --- heavy phase: warp processes its 8 voxels, 2 routed experts each ---
    const int wid  = tid >> 5;
    const int lane = tid & 31;
    const int oc   = lane << 2;            // 4 consecutive output rows per lane
    float* hw = hs[wid];

    for (int k = 0; k < 8; k++) {
        const int v = wid * 8 + k;
        float* xv = xs + v * PITCH;
        const float4* xv4 = (const float4*)xv;
        float4 acc_out = *(const float4*)(xv + oc);   // residual init

        #pragma unroll
        for (int t = 0; t < 2; t++) {
            const int   e = re[v][t];
            const float p = rp[v][t];

            // ---- layer 1: h = silu(W1[e] @ x_v + b1[e]) * p ----
            const float* wb1 = w1 + ((size_t)e * CDIM + oc) * CDIM;
            const float4* r0 = (const float4*)(wb1);
            const float4* r1 = (const float4*)(wb1 + CDIM);
            const float4* r2 = (const float4*)(wb1 + 2 * CDIM);
            const float4* r3 = (const float4*)(wb1 + 3 * CDIM);
            float a0 = 0.f, a1 = 0.f, a2 = 0.f, a3 = 0.f;
            #pragma unroll
            for (int j = 0; j < CDIM / 4; j++) {
                float4 xj = xv4[j];
                a0 = dot4(xj, r0[j], a0);
                a1 = dot4(xj, r1[j], a1);
                a2 = dot4(xj, r2[j], a2);
                a3 = dot4(xj, r3[j], a3);
            }
            float4 bb1 = *(const float4*)(b1 + e * CDIM + oc);
            a0 += bb1.x; a1 += bb1.y; a2 += bb1.z; a3 += bb1.w;
            a0 = p * a0 / (1.f + __expf(-a0));
            a1 = p * a1 / (1.f + __expf(-a1));
            a2 = p * a2 / (1.f + __expf(-a2));
            a3 = p * a3 / (1.f + __expf(-a3));
            *(float4*)(hw + oc) = make_float4(a0, a1, a2, a3);
            __syncwarp();

            // ---- layer 2: out += W2[e] @ h + p * b2[e] ----
            const float4* h4 = (const float4*)hw;
            const float* wb2 = w2 + ((size_t)e * CDIM + oc) * CDIM;
            const float4* u0 = (const float4*)(wb2);
            const float4* u1 = (const float4*)(wb2 + CDIM);
            const float4* u2 = (const float4*)(wb2 + 2 * CDIM);
            const float4* u3 = (const float4*)(wb2 + 3 * CDIM);
            float c0 = 0.f, c1 = 0.f, c2 = 0.f, c3 = 0.f;
            #pragma unroll
            for (int j = 0; j < CDIM / 4; j++) {
                float4 hj = h4[j];
                c0 = dot4(hj, u0[j], c0);
                c1 = dot4(hj, u1[j], c1);
                c2 = dot4(hj, u2[j], c2);
                c3 = dot4(hj, u3[j], c3);
            }
            float4 bb2 = *(const float4*)(b2 + e * CDIM + oc);
            acc_out.x += c0 + p * bb2.x;
            acc_out.y += c1 + p * bb2.y;
            acc_out.z += c2 + p * bb2.z;
            acc_out.w += c3 + p * bb2.w;
            __syncwarp();   // all lanes done reading hw before next overwrite
        }
        // write result back into the tile (xs[v] no longer needed)
        *(float4*)(xv + oc) = acc_out;
    }
    __syncthreads();

    // --- store out tile (coalesced, mirror of the load) ---
    float* ob = out + ((size_t)b * CDIM) * SPATIAL + s0;
    #pragma unroll
    for (int cc = 0; cc < CDIM; cc += 4) {
        int c = cc + c_sub;
        ob[(size_t)c * SPATIAL + iv] = xs[iv * PITCH + c];
    }
}

extern "C" void kernel_launch(void* const* d_in, const int* in_sizes, int n_in,
                              void* d_out, int out_size) {
    const float* x   = (const float*)d_in[0];
    const float* gwp = (const float*)d_in[1];
    const float* gbp = (const float*)d_in[2];
    const float* w1p = (const float*)d_in[3];
    const float* b1p = (const float*)d_in[4];
    const float* w2p = (const float*)d_in[5];
    const float* b2p = (const float*)d_in[6];
    float* outp = (float*)d_out;

    int nvox = in_sizes[0] / CDIM;   // B * T * H * W = 65536
    int grid = nvox / TILE_V;        // 1024
    moe_sparse_kernel<<<grid, NT>>>(x, gwp, gbp, w1p, b1p, w2p, b2p, outp);
}

// round 2
// speedup vs baseline: 6.1999x; 6.1999x over previous
#include <cuda_runtime.h>

#define CDIM    128
#define NEXP    8
#define SPATIAL 32768            // T*H*W
#define NVOX    65536            // B*T*H*W
#define CHUNK   512              // voxels per routing chunk
#define NCHUNK  (NVOX / CHUNK)   // 128
#define SUBV    128              // voxels per GEMM sub-tile
#define WPITCH  132              // padded smem pitch for transposed operands

// ---------------- device scratch (allocation-free) ----------------
__device__ float          g_y0[(size_t)NVOX * CDIM];   // slot-0 expert outputs [v][c]
__device__ float          g_y1[(size_t)NVOX * CDIM];   // slot-1 expert outputs [v][c]
__device__ unsigned short g_lists[NCHUNK * NEXP * CHUNK];
__device__ int            g_counts[NCHUNK * NEXP];
__device__ float2         g_probs[NVOX];

__device__ __forceinline__ float dot4(float4 a, float4 b, float acc) {
    acc = fmaf(a.x, b.x, acc);
    acc = fmaf(a.y, b.y, acc);
    acc = fmaf(a.z, b.z, acc);
    acc = fmaf(a.w, b.w, acc);
    return acc;
}

// ================= K1: gate + routing + compaction =================
__global__ __launch_bounds__(256)
void gate_kernel(const float* __restrict__ x,
                 const float* __restrict__ gate_w,
                 const float* __restrict__ gate_b)
{
    __shared__ float xs[64 * WPITCH];          // 64-voxel sub-tile [v][c]
    __shared__ float lgs[64 * NEXP];
    __shared__ int   re[64][2];
    __shared__ unsigned short l8[NEXP][CHUNK];
    __shared__ int   lcnt[NEXP];

    const int tid = threadIdx.x;
    const int chunk = blockIdx.x;
    if (tid < NEXP) lcnt[tid] = 0;

    const int c_sub = tid >> 6;
    const int iv    = tid & 63;

    for (int st = 0; st < CHUNK / 64; st++) {
        const int vg0 = chunk * CHUNK + st * 64;
        const int b   = vg0 >> 15;
        const int s0  = vg0 & (SPATIAL - 1);
        const float* xb = x + ((size_t)b * CDIM) * SPATIAL + s0;

        __syncthreads();   // protect xs/re reuse
        #pragma unroll
        for (int cc = 0; cc < CDIM; cc += 4) {
            int c = cc + c_sub;
            xs[iv * WPITCH + c] = xb[(size_t)c * SPATIAL + iv];
        }
        __syncthreads();

        // logits: 512 (v,e) pairs
        {
            int v = tid & 63;
            int e = tid >> 6;
            const float4* xv4 = (const float4*)(xs + v * WPITCH);
            const float4* gw4 = (const float4*)(gate_w + e * CDIM);
            #pragma unroll 2
            for (int ee = 0; ee < 2; ee++) {   // 4 e-slots * 2 = 8 experts
                float acc = 0.f;
                const float4* g4 = gw4 + ee * 4 * (CDIM / 4);
                #pragma unroll
                for (int j = 0; j < CDIM / 4; j++) acc = dot4(xv4[j], g4[j], acc);
                lgs[v * NEXP + (e + ee * 4)] = acc + __ldg(gate_b + e + ee * 4);
            }
        }
        __syncthreads();

        if (tid < 64) {
            const float* l = lgs + tid * NEXP;
            int i0 = 0; float v0 = l[0];
            #pragma unroll
            for (int e = 1; e < NEXP; e++) { float t = l[e]; if (t > v0) { v0 = t; i0 = e; } }
            int i1 = -1; float v1 = -3.4e38f;
            #pragma unroll
            for (int e = 0; e < NEXP; e++) {
                if (e == i0) continue;
                float t = l[e]; if (t > v1) { v1 = t; i1 = e; }
            }
            float e1v = __expf(v1 - v0);
            float inv = 1.f / (1.f + e1v);
            re[tid][0] = i0; re[tid][1] = i1;
            g_probs[chunk * CHUNK + st * 64 + tid] = make_float2(inv, e1v * inv);
        }
        __syncthreads();

        // ordered append (keeps lists sorted -> coalesced gathers in K2)
        if (tid < NEXP) {
            int e = tid, cnt = lcnt[e];
            for (int v = 0; v < 64; v++) {
                int voff = st * 64 + v;
                if (re[v][0] == e)      l8[e][cnt++] = (unsigned short)voff;
                else if (re[v][1] == e) l8[e][cnt++] = (unsigned short)(voff | (1 << 9));
            }
            lcnt[e] = cnt;
        }
    }
    __syncthreads();

    for (int i = tid; i < NEXP * CHUNK; i += 256) {
        int e = i >> 9, j = i & (CHUNK - 1);
        if (j < lcnt[e]) g_lists[(chunk * NEXP + e) * CHUNK + j] = l8[e][j];
    }
    if (tid < NEXP) g_counts[chunk * NEXP + tid] = lcnt[tid];
}

// ================= K2: per-(chunk,expert) fused GEMM =================
__global__ __launch_bounds__(256)
void expert_kernel(const float* __restrict__ x,
                   const float* __restrict__ w1,
                   const float* __restrict__ b1,
                   const float* __restrict__ w2,
                   const float* __restrict__ b2)
{
    extern __shared__ float dsm[];
    float* xT = dsm;                         // [128 k][128 v]
    float* Wt = dsm + CDIM * CDIM;           // [128 k][WPITCH]
    float* Hs = Wt + CDIM * WPITCH;          // [128 j][WPITCH]

    __shared__ unsigned short lst[CHUNK];
    __shared__ float pvs[SUBV];
    __shared__ int   gvs[SUBV];
    __shared__ int   sls[SUBV];

    const int tid   = threadIdx.x;
    const int chunk = blockIdx.x >> 3;
    const int e     = blockIdx.x & 7;
    const int m     = g_counts[chunk * NEXP + e];
    if (m == 0) return;

    for (int i = tid; i < m; i += 256)
        lst[i] = g_lists[(chunk * NEXP + e) * CHUNK + i];

    const int ty = tid >> 4, tx = tid & 15;
    const int v0 = ty * 8, o0 = tx * 8;      // warp owns contiguous 16-voxel band

    float bb2[8];
    #pragma unroll
    for (int i = 0; i < 8; i++) bb2[i] = __ldg(b2 + e * CDIM + o0 + i);
    float bb1[8];
    #pragma unroll
    for (int i = 0; i < 8; i++) bb1[i] = __ldg(b1 + e * CDIM + o0 + i);

    for (int base = 0; base < m; base += SUBV) {
        const int msub = min(SUBV, m - base);
        __syncthreads();     // previous iter fully consumed

        if (tid < SUBV) {
            if (tid < msub) {
                int entry = lst[base + tid];
                int voff  = entry & 511;
                int slot  = (entry >> 9) & 1;
                int g     = chunk * CHUNK + voff;
                float2 pp = g_probs[g];
                pvs[tid] = slot ? pp.y : pp.x;
                gvs[tid] = g; sls[tid] = slot;
            }
        }
        __syncthreads();

        // gather x -> xT[k][v] (sorted list => near-coalesced along v)
        #pragma unroll 4
        for (int it = 0; it < 64; it++) {
            int i = tid & 127;
            int c = (tid >> 7) + it * 2;
            float val = 0.f;
            if (i < msub) {
                int g = gvs[i];
                int b = g >> 15, s = g & (SPATIAL - 1);
                val = __ldg(x + ((size_t)(b * CDIM + c)) * SPATIAL + s);
            }
            xT[c * CDIM + i] = val;
        }

        // W1[e] -> Wt[k][o]  (coalesced read, transposed smem write)
        {
            int o = tid >> 1, kh = (tid & 1) * 64;
            const float4* src = (const float4*)(w1 + ((size_t)(e * CDIM + o)) * CDIM + kh);
            #pragma unroll
            for (int j = 0; j < 16; j++) {
                float4 w = src[j];
                int k = kh + j * 4;
                Wt[(k + 0) * WPITCH + o] = w.x;
                Wt[(k + 1) * WPITCH + o] = w.y;
                Wt[(k + 2) * WPITCH + o] = w.z;
                Wt[(k + 3) * WPITCH + o] = w.w;
            }
        }
        __syncthreads();

        const bool act = (v0 < msub);
        float acc[8][8];
        #pragma unroll
        for (int i = 0; i < 8; i++)
            #pragma unroll
            for (int j = 0; j < 8; j++) acc[i][j] = 0.f;

        // ---- GEMM1: acc[o][v] = sum_k W1t[k][o] * xT[k][v] ----
        if (act) {
            #pragma unroll 2
            for (int k = 0; k < CDIM; k++) {
                float a[8], bf[8];
                *(float4*)&a[0]  = *(const float4*)(xT + k * CDIM + v0);
                *(float4*)&a[4]  = *(const float4*)(xT + k * CDIM + v0 + 4);
                *(float4*)&bf[0] = *(const float4*)(Wt + k * WPITCH + o0);
                *(float4*)&bf[4] = *(const float4*)(Wt + k * WPITCH + o0 + 4);
                #pragma unroll
                for (int i = 0; i < 8; i++)
                    #pragma unroll
                    for (int j = 0; j < 8; j++)
                        acc[i][j] = fmaf(bf[i], a[j], acc[i][j]);
            }
            // silu(+b1) * p  ->  Hs[o][v]
            #pragma unroll
            for (int i = 0; i < 8; i++) {
                float h[8];
                #pragma unroll
                for (int j = 0; j < 8; j++) {
                    float t = acc[i][j] + bb1[i];
                    h[j] = pvs[v0 + j] * t / (1.f + __expf(-t));
                }
                *(float4*)(Hs + (o0 + i) * WPITCH + v0)     = *(float4*)&h[0];
                *(float4*)(Hs + (o0 + i) * WPITCH + v0 + 4) = *(float4*)&h[4];
            }
        }
        __syncthreads();

        // W2[e] -> Wt[k][o] (overwrite)
        {
            int o = tid >> 1, kh = (tid & 1) * 64;
            const float4* src = (const float4*)(w2 + ((size_t)(e * CDIM + o)) * CDIM + kh);
            #pragma unroll
            for (int j = 0; j < 16; j++) {
                float4 w = src[j];
                int k = kh + j * 4;
                Wt[(k + 0) * WPITCH + o] = w.x;
                Wt[(k + 1) * WPITCH + o] = w.y;
                Wt[(k + 2) * WPITCH + o] = w.z;
                Wt[(k + 3) * WPITCH + o] = w.w;
            }
        }
        __syncthreads();

        // ---- GEMM2: out[o][v] = sum_j W2t[j][o] * Hs[j][v] ----
        if (act) {
            #pragma unroll
            for (int i = 0; i < 8; i++)
                #pragma unroll
                for (int j = 0; j < 8; j++) acc[i][j] = 0.f;
            #pragma unroll 2
            for (int k = 0; k < CDIM; k++) {
                float a[8], bf[8];
                *(float4*)&a[0]  = *(const float4*)(Hs + k * WPITCH + v0);
                *(float4*)&a[4]  = *(const float4*)(Hs + k * WPITCH + v0 + 4);
                *(float4*)&bf[0] = *(const float4*)(Wt + k * WPITCH + o0);
                *(float4*)&bf[4] = *(const float4*)(Wt + k * WPITCH + o0 + 4);
                #pragma unroll
                for (int i = 0; i < 8; i++)
                    #pragma unroll
                    for (int j = 0; j < 8; j++)
                        acc[i][j] = fmaf(bf[i], a[j], acc[i][j]);
            }
            // store p*(W2 h + b2) into slot scratch
            #pragma unroll
            for (int j = 0; j < 8; j++) {
                int vi = v0 + j;
                if (vi < msub) {
                    float p = pvs[vi];
                    float* yb = (sls[vi] ? g_y1 : g_y0) + (size_t)gvs[vi] * CDIM + o0;
                    float o4[8];
                    #pragma unroll
                    for (int i = 0; i < 8; i++) o4[i] = acc[i][j] + p * bb2[i];
                    *(float4*)(yb)     = *(float4*)&o4[0];
                    *(float4*)(yb + 4) = *(float4*)&o4[4];
                }
            }
        }
    }
}

// ================= K3: out = x + y0 + y1 (transpose back) =================
__global__ __launch_bounds__(256)
void combine_kernel(const float* __restrict__ x, float* __restrict__ out)
{
    __shared__ float ts[64 * WPITCH];
    const int tid = threadIdx.x;
    const int v0  = blockIdx.x * 64;
    const int b   = v0 >> 15;
    const int s0  = v0 & (SPATIAL - 1);

    const float4* y04 = (const float4*)(g_y0 + (size_t)v0 * CDIM);
    const float4* y14 = (const float4*)(g_y1 + (size_t)v0 * CDIM);
    #pragma unroll
    for (int it = 0; it < 8; it++) {
        int idx = tid + it * 256;            // 2048 float4s
        int vl  = idx >> 5;
        int c4  = idx & 31;
        float4 a = y04[idx], c = y14[idx];
        a.x += c.x; a.y += c.y; a.z += c.z; a.w += c.w;
        *(float4*)(ts + vl * WPITCH + c4 * 4) = a;
    }
    __syncthreads();

    const int c_sub = tid >> 6;
    const int iv    = tid & 63;
    const float* xb = x   + ((size_t)b * CDIM) * SPATIAL + s0;
    float*       ob = out + ((size_t)b * CDIM) * SPATIAL + s0;
    #pragma unroll
    for (int cc = 0; cc < CDIM; cc += 4) {
        int c = cc + c_sub;
        ob[(size_t)c * SPATIAL + iv] = ts[iv * WPITCH + c] + xb[(size_t)c * SPATIAL + iv];
    }
}

// ================= launch =================
extern "C" void kernel_launch(void* const* d_in, const int* in_sizes, int n_in,
                              void* d_out, int out_size) {
    const float* x   = (const float*)d_in[0];
    const float* gwp = (const float*)d_in[1];
    const float* gbp = (const float*)d_in[2];
    const float* w1p = (const float*)d_in[3];
    const float* b1p = (const float*)d_in[4];
    const float* w2p = (const float*)d_in[5];
    const float* b2p = (const float*)d_in[6];
    float* outp = (float*)d_out;

    static int smem_set = 0;
    const int dyn_smem = (CDIM * CDIM + 2 * CDIM * WPITCH) * sizeof(float); // 200704 B
    if (!smem_set) {
        cudaFuncSetAttribute(expert_kernel,
                             cudaFuncAttributeMaxDynamicSharedMemorySize, dyn_smem);
        smem_set = 1;
    }

    gate_kernel<<<NCHUNK, 256>>>(x, gwp, gbp);
    expert_kernel<<<NCHUNK * NEXP, 256, dyn_smem>>>(x, w1p, b1p, w2p, b2p);
    combine_kernel<<<NVOX / 64, 256>>>(x, outp);
}

// round 4
// speedup vs baseline: 21.9813x; 3.5455x over previous
#include <cuda_runtime.h>
#include <cuda_bf16.h>
#include <cstdint>

#define CDIM    128
#define NEXP    8
#define SPATIAL 32768
#define NVOX    65536
#define CHUNK   512
#define NCHUNK  128
#define SUBV    128
#define WPITCH  132
#define PKB     272           // smem tile row pitch in BYTES (128 bf16 + 8 pad)

// ---------------- device scratch ----------------
__device__ float          g_y0[(size_t)NVOX * CDIM];
__device__ float          g_y1[(size_t)NVOX * CDIM];
__device__ unsigned short g_route[NVOX];
__device__ float          g_prob[NVOX];

__device__ __forceinline__ uint32_t smem_u32(const void* p) {
    uint32_t a;
    asm("{ .reg .u64 t; cvta.to.shared.u64 t, %1; cvt.u32.u64 %0, t; }" : "=r"(a) : "l"(p));
    return a;
}

#define LDSM_X4(r0, r1, r2, r3, addr) \
    asm volatile("ldmatrix.sync.aligned.m8n8.x4.shared.b16 {%0,%1,%2,%3}, [%4];" \
        : "=r"(r0), "=r"(r1), "=r"(r2), "=r"(r3) : "r"(addr))

#define MMA16816(c, a, b) \
    asm volatile("mma.sync.aligned.m16n8k16.row.col.f32.bf16.bf16.f32 " \
        "{%0,%1,%2,%3}, {%4,%5,%6,%7}, {%8,%9}, {%0,%1,%2,%3};" \
        : "+f"((c)[0]), "+f"((c)[1]), "+f"((c)[2]), "+f"((c)[3]) \
        : "r"((a)[0]), "r"((a)[1]), "r"((a)[2]), "r"((a)[3]), "r"((b)[0]), "r"((b)[1]))

__device__ __forceinline__ float dot4(float4 a, float4 b, float acc) {
    acc = fmaf(a.x, b.x, acc);
    acc = fmaf(a.y, b.y, acc);
    acc = fmaf(a.z, b.z, acc);
    acc = fmaf(a.w, b.w, acc);
    return acc;
}

// ================= K1: gate (per-voxel route + prob) =================
__global__ __launch_bounds__(256)
void gate_kernel(const float* __restrict__ x,
                 const float* __restrict__ gw,
                 const float* __restrict__ gb)
{
    __shared__ float xs[64 * WPITCH];
    __shared__ float lgs[64 * NEXP];
    const int tid = threadIdx.x;
    const int vg0 = blockIdx.x * 64;
    const int b = vg0 >> 15, s0 = vg0 & (SPATIAL - 1);
    const float* xb = x + ((size_t)b * CDIM) * SPATIAL + s0;
    const int c_sub = tid >> 6, iv = tid & 63;
    #pragma unroll
    for (int cc = 0; cc < CDIM; cc += 4) {
        int c = cc + c_sub;
        xs[iv * WPITCH + c] = xb[(size_t)c * SPATIAL + iv];
    }
    __syncthreads();
    {
        int v = tid & 63, e = tid >> 6;
        const float4* xv4 = (const float4*)(xs + v * WPITCH);
        #pragma unroll 2
        for (int ee = 0; ee < 2; ee++) {
            int eidx = e + ee * 4;
            const float4* g4 = (const float4*)(gw + eidx * CDIM);
            float acc = 0.f;
            #pragma unroll
            for (int j = 0; j < CDIM / 4; j++) acc = dot4(xv4[j], g4[j], acc);
            lgs[v * NEXP + eidx] = acc + __ldg(gb + eidx);
        }
    }
    __syncthreads();
    if (tid < 64) {
        const float* l = lgs + tid * NEXP;
        int i0 = 0; float v0 = l[0];
        #pragma unroll
        for (int e = 1; e < NEXP; e++) { float t = l[e]; if (t > v0) { v0 = t; i0 = e; } }
        int i1 = -1; float v1 = -3.4e38f;
        #pragma unroll
        for (int e = 0; e < NEXP; e++) {
            if (e == i0) continue;
            float t = l[e]; if (t > v1) { v1 = t; i1 = e; }
        }
        float e1v = __expf(v1 - v0);
        g_route[vg0 + tid] = (unsigned short)(i0 | (i1 << 8));
        g_prob[vg0 + tid]  = 1.f / (1.f + e1v);   // p0; p1 = 1 - p0
    }
}

// ================= K2: bf16 mma.sync expert GEMMs =================
__global__ __launch_bounds__(256, 2)
void expert_kernel(const float* __restrict__ x,
                   const float* __restrict__ w1, const float* __restrict__ b1,
                   const float* __restrict__ w2, const float* __restrict__ b2)
{
    extern __shared__ char dynsm[];
    __shared__ unsigned short lst[CHUNK];
    __shared__ float b1s[CDIM], b2s[CDIM];
    __shared__ float pvs[SUBV];
    __shared__ int   gvs[SUBV];
    __shared__ int   sls[SUBV];
    __shared__ int   m_sh;

    const int tid = threadIdx.x;
    const int wid = tid >> 5, lane = tid & 31;
    const int chunk = blockIdx.x >> 3;
    const int e = blockIdx.x & 7;

    char* Ab  = dynsm;                 // A / H tile  [128 v][PKB]
    char* W1b = dynsm + 128 * PKB;     // W1 tile     [128 o][PKB]
    char* W2b = dynsm + 256 * PKB;     // W2 tile

    // ---- compact voxel list for this (chunk, expert) ----
    if (wid == 0) {
        int cnt = 0;
        for (int it = 0; it < CHUNK / 32; it++) {
            int v = it * 32 + lane;
            unsigned rt = g_route[chunk * CHUNK + v];
            bool h1 = ((rt >> 8) == (unsigned)e);
            bool hit = ((rt & 255u) == (unsigned)e) || h1;
            unsigned msk = __ballot_sync(0xFFFFFFFFu, hit);
            if (hit) lst[cnt + __popc(msk & ((1u << lane) - 1u))] =
                         (unsigned short)(v | (h1 ? 512 : 0));
            cnt += __popc(msk);
        }
        if (lane == 0) m_sh = cnt;
    }

    // ---- stage W1, W2 (fp32 -> bf16, [o][k] row-major, pitch 272B) ----
    {
        int o = tid >> 1, kh = (tid & 1) * 64;
        const float4* s1 = (const float4*)(w1 + ((size_t)(e * CDIM + o)) * CDIM + kh);
        const float4* s2 = (const float4*)(w2 + ((size_t)(e * CDIM + o)) * CDIM + kh);
        char* d1 = W1b + o * PKB + kh * 2;
        char* d2 = W2b + o * PKB + kh * 2;
        #pragma unroll
        for (int j = 0; j < 16; j++) {
            float4 a = s1[j];
            uint2 v;
            __nv_bfloat162 t0 = __float22bfloat162_rn(make_float2(a.x, a.y));
            __nv_bfloat162 t1 = __float22bfloat162_rn(make_float2(a.z, a.w));
            v.x = *(uint32_t*)&t0; v.y = *(uint32_t*)&t1;
            *(uint2*)(d1 + 8 * j) = v;
            float4 c = s2[j];
            t0 = __float22bfloat162_rn(make_float2(c.x, c.y));
            t1 = __float22bfloat162_rn(make_float2(c.z, c.w));
            v.x = *(uint32_t*)&t0; v.y = *(uint32_t*)&t1;
            *(uint2*)(d2 + 8 * j) = v;
        }
    }
    if (tid < CDIM) {
        b1s[tid] = __ldg(b1 + e * CDIM + tid);
        b2s[tid] = __ldg(b2 + e * CDIM + tid);
    }
    __syncthreads();

    const int m = m_sh;
    if (m == 0) return;

    const uint32_t A_u  = smem_u32(Ab);
    const uint32_t W1_u = smem_u32(W1b);
    const uint32_t W2_u = smem_u32(W2b);

    // warp tiling: 2 (m) x 4 (n); warp tile 64 x 32
    const int warp_m = wid & 1, warp_n = wid >> 1;
    // per-lane ldmatrix offsets (bytes)
    const uint32_t a_loff = (uint32_t)((lane & 15) * PKB + (lane >> 4) * 16);
    const uint32_t b_loff = (uint32_t)(((lane & 7) + ((lane >> 4) << 3)) * PKB +
                                       ((lane >> 3) & 1) * 16);
    // epilogue lane coords
    const int rb = warp_m * 64 + (lane >> 2);
    const int cb = warp_n * 32 + 2 * (lane & 3);

    for (int bse = 0; bse < m; bse += SUBV) {
        const int msub = min(SUBV, m - bse);
        __syncthreads();   // previous sub-tile fully consumed

        // ---- gather x -> A tile (bf16), fill per-voxel meta ----
        {
            const int v = tid & 127;
            const int c0 = (tid >> 7) * 64;
            if (v < msub) {
                int en2 = lst[bse + v];
                int slot = en2 >> 9;
                int gvox = chunk * CHUNK + (en2 & 511);
                if (c0 == 0) {
                    float p0 = g_prob[gvox];
                    pvs[v] = slot ? 1.f - p0 : p0;
                    gvs[v] = gvox; sls[v] = slot;
                }
                const int bb = gvox >> 15, ss = gvox & (SPATIAL - 1);
                const float* xp = x + ((size_t)(bb * CDIM + c0)) * SPATIAL + ss;
                char* dst = Ab + v * PKB + c0 * 2;
                #pragma unroll 8
                for (int cc = 0; cc < 64; cc += 2) {
                    float f0 = __ldg(xp + (size_t)cc * SPATIAL);
                    float f1 = __ldg(xp + (size_t)(cc + 1) * SPATIAL);
                    __nv_bfloat162 t = __float22bfloat162_rn(make_float2(f0, f1));
                    *(uint32_t*)(dst + 2 * cc) = *(uint32_t*)&t;
                }
            }
        }
        __syncthreads();

        float acc[4][4][4];
        #pragma unroll
        for (int i = 0; i < 4; i++)
            #pragma unroll
            for (int j = 0; j < 4; j++)
                #pragma unroll
                for (int q = 0; q < 4; q++) acc[i][j][q] = 0.f;

        // ---- GEMM1: acc[v][o] = X @ W1^T ----
        #pragma unroll
        for (int ks = 0; ks < 8; ks++) {
            const uint32_t kb = ks * 32;   // k0*2 bytes
            uint32_t af[4][4], bf[4][2];
            #pragma unroll
            for (int mf = 0; mf < 4; mf++) {
                uint32_t ad = A_u + (uint32_t)((warp_m * 64 + mf * 16) * PKB) + kb + a_loff;
                LDSM_X4(af[mf][0], af[mf][1], af[mf][2], af[mf][3], ad);
            }
            #pragma unroll
            for (int np = 0; np < 2; np++) {
                uint32_t bd = W1_u + (uint32_t)((warp_n * 32 + np * 16) * PKB) + kb + b_loff;
                uint32_t r0, r1, r2, r3;
                LDSM_X4(r0, r1, r2, r3, bd);
                bf[2 * np][0] = r0; bf[2 * np][1] = r1;
                bf[2 * np + 1][0] = r2; bf[2 * np + 1][1] = r3;
            }
            #pragma unroll
            for (int mf = 0; mf < 4; mf++)
                #pragma unroll
                for (int nf = 0; nf < 4; nf++)
                    MMA16816(acc[mf][nf], af[mf], bf[nf]);
        }
        __syncthreads();   // all warps done reading A

        // ---- epilogue 1: silu(acc+b1)*p -> bf16 H (reuse A tile) ----
        #pragma unroll
        for (int mf = 0; mf < 4; mf++) {
            int r0 = rb + mf * 16, r1 = r0 + 8;
            float p0 = pvs[r0], p1 = pvs[r1];
            #pragma unroll
            for (int nf = 0; nf < 4; nf++) {
                int c = cb + nf * 8;
                float bia0 = b1s[c], bia1 = b1s[c + 1];
                float t0 = acc[mf][nf][0] + bia0, t1 = acc[mf][nf][1] + bia1;
                float t2 = acc[mf][nf][2] + bia0, t3 = acc[mf][nf][3] + bia1;
                float h0 = p0 * t0 / (1.f + __expf(-t0));
                float h1 = p0 * t1 / (1.f + __expf(-t1));
                float h2 = p1 * t2 / (1.f + __expf(-t2));
                float h3 = p1 * t3 / (1.f + __expf(-t3));
                __nv_bfloat162 u0 = __float22bfloat162_rn(make_float2(h0, h1));
                __nv_bfloat162 u1 = __float22bfloat162_rn(make_float2(h2, h3));
                *(uint32_t*)(Ab + r0 * PKB + c * 2) = *(uint32_t*)&u0;
                *(uint32_t*)(Ab + r1 * PKB + c * 2) = *(uint32_t*)&u1;
            }
        }
        __syncthreads();   // H fully written

        #pragma unroll
        for (int i = 0; i < 4; i++)
            #pragma unroll
            for (int j = 0; j < 4; j++)
                #pragma unroll
                for (int q = 0; q < 4; q++) acc[i][j][q] = 0.f;

        // ---- GEMM2: acc[v][o] = H @ W2^T ----
        #pragma unroll
        for (int ks = 0; ks < 8; ks++) {
            const uint32_t kb = ks * 32;
            uint32_t af[4][4], bf[4][2];
            #pragma unroll
            for (int mf = 0; mf < 4; mf++) {
                uint32_t ad = A_u + (uint32_t)((warp_m * 64 + mf * 16) * PKB) + kb + a_loff;
                LDSM_X4(af[mf][0], af[mf][1], af[mf][2], af[mf][3], ad);
            }
            #pragma unroll
            for (int np = 0; np < 2; np++) {
                uint32_t bd = W2_u + (uint32_t)((warp_n * 32 + np * 16) * PKB) + kb + b_loff;
                uint32_t r0, r1, r2, r3;
                LDSM_X4(r0, r1, r2, r3, bd);
                bf[2 * np][0] = r0; bf[2 * np][1] = r1;
                bf[2 * np + 1][0] = r2; bf[2 * np + 1][1] = r3;
            }
            #pragma unroll
            for (int mf = 0; mf < 4; mf++)
                #pragma unroll
                for (int nf = 0; nf < 4; nf++)
                    MMA16816(acc[mf][nf], af[mf], bf[nf]);
        }

        // ---- epilogue 2: + p*b2, scatter to y[slot] (gmem only) ----
        #pragma unroll
        for (int mf = 0; mf < 4; mf++) {
            int r0 = rb + mf * 16, r1 = r0 + 8;
            #pragma unroll
            for (int half = 0; half < 2; half++) {
                int r = half ? r1 : r0;
                if (r < msub) {
                    float p = pvs[r];
                    float* yb = (sls[r] ? g_y1 : g_y0) + (size_t)gvs[r] * CDIM;
                    #pragma unroll
                    for (int nf = 0; nf < 4; nf++) {
                        int c = cb + nf * 8;
                        float2 o2;
                        o2.x = acc[mf][nf][2 * half]     + p * b2s[c];
                        o2.y = acc[mf][nf][2 * half + 1] + p * b2s[c + 1];
                        *(float2*)(yb + c) = o2;
                    }
                }
            }
        }
    }
}

// ================= K3: out = x + y0 + y1 =================
__global__ __launch_bounds__(256)
void combine_kernel(const float* __restrict__ x, float* __restrict__ out)
{
    __shared__ float ts[64 * WPITCH];
    const int tid = threadIdx.x;
    const int v0  = blockIdx.x * 64;
    const int b   = v0 >> 15;
    const int s0  = v0 & (SPATIAL - 1);

    const float4* y04 = (const float4*)(g_y0 + (size_t)v0 * CDIM);
    const float4* y14 = (const float4*)(g_y1 + (size_t)v0 * CDIM);
    #pragma unroll
    for (int it = 0; it < 8; it++) {
        int idx = tid + it * 256;
        int vl  = idx >> 5;
        int c4  = idx & 31;
        float4 a = y04[idx], c = y14[idx];
        a.x += c.x; a.y += c.y; a.z += c.z; a.w += c.w;
        *(float4*)(ts + vl * WPITCH + c4 * 4) = a;
    }
    __syncthreads();

    const int c_sub = tid >> 6;
    const int iv    = tid & 63;
    const float* xb = x   + ((size_t)b * CDIM) * SPATIAL + s0;
    float*       ob = out + ((size_t)b * CDIM) * SPATIAL + s0;
    #pragma unroll
    for (int cc = 0; cc < CDIM; cc += 4) {
        int c = cc + c_sub;
        ob[(size_t)c * SPATIAL + iv] = ts[iv * WPITCH + c] + xb[(size_t)c * SPATIAL + iv];
    }
}

// ================= launch =================
extern "C" void kernel_launch(void* const* d_in, const int* in_sizes, int n_in,
                              void* d_out, int out_size) {
    const float* x   = (const float*)d_in[0];
    const float* gwp = (const float*)d_in[1];
    const float* gbp = (const float*)d_in[2];
    const float* w1p = (const float*)d_in[3];
    const float* b1p = (const float*)d_in[4];
    const float* w2p = (const float*)d_in[5];
    const float* b2p = (const float*)d_in[6];
    float* outp = (float*)d_out;

    static int smem_set = 0;
    const int dyn_smem = 3 * 128 * PKB;   // A/H + W1 + W2 = 104448 B
    if (!smem_set) {
        cudaFuncSetAttribute(expert_kernel,
                             cudaFuncAttributeMaxDynamicSharedMemorySize, dyn_smem);
        smem_set = 1;
    }

    gate_kernel<<<NVOX / 64, 256>>>(x, gwp, gbp);
    expert_kernel<<<NCHUNK * NEXP, 256, dyn_smem>>>(x, w1p, b1p, w2p, b2p);
    combine_kernel<<<NVOX / 64, 256>>>(x, outp);
}